// round 2
// baseline (speedup 1.0000x reference)
#include <cuda_runtime.h>
#include <cuda_bf16.h>

#define BB 4
#define NN 2048
#define PARAM_G 0.125f
#define VIRUS_DEATH 8e-05f

// Scratch (allocation-free rule: __device__ globals)
__device__ float g_colsum[BB * NN];
__device__ float g_m[BB];

// ---------------------------------------------------------------------------
// Kernel 0: zero the column-sum scratch (must be reset every graph replay)
// ---------------------------------------------------------------------------
__global__ void zero_kernel() {
    int t = blockIdx.x * blockDim.x + threadIdx.x;
    if (t < BB * NN) g_colsum[t] = 0.0f;
}

// ---------------------------------------------------------------------------
// Kernel 1: col_sum[b][j] = sum_{i != j} mob[b][i][j]
// Thread = 4 columns (float4, coalesced), each block covers a 128-row chunk.
// ---------------------------------------------------------------------------
__global__ void __launch_bounds__(256) colsum_kernel(const float* __restrict__ mob) {
    const int t  = threadIdx.x;
    const int c4 = blockIdx.x * 256 + t;          // float4 column group
    const int j0 = c4 * 4;                        // first of 4 columns
    const int b  = blockIdx.z;
    const int i0 = blockIdx.y * (NN / 16);
    const float4* base = (const float4*)(mob + (size_t)b * NN * NN) + c4;
    float4 s = make_float4(0.f, 0.f, 0.f, 0.f);
#pragma unroll 8
    for (int i = i0; i < i0 + NN / 16; ++i) {
        float4 v = base[(size_t)i * (NN / 4)];
        if (i == j0)     v.x = 0.0f;
        if (i == j0 + 1) v.y = 0.0f;
        if (i == j0 + 2) v.z = 0.0f;
        if (i == j0 + 3) v.w = 0.0f;
        s.x += v.x; s.y += v.y; s.z += v.z; s.w += v.w;
    }
    float* dst = &g_colsum[b * NN + j0];
    atomicAdd(dst + 0, s.x);
    atomicAdd(dst + 1, s.y);
    atomicAdd(dst + 2, s.z);
    atomicAdd(dst + 3, s.w);
}

// ---------------------------------------------------------------------------
// Kernel 2: per batch, fai = sum(col_sum), tau = sum(S+I+R), m = fai/tau
// ---------------------------------------------------------------------------
__global__ void __launch_bounds__(256) m_kernel(const float* __restrict__ SIR) {
    const int b = blockIdx.x;
    const int t = threadIdx.x;
    const float4* sir4 = (const float4*)(SIR + (size_t)b * NN * 4);
    float fai = 0.0f, tau = 0.0f;
    for (int j = t; j < NN; j += 256) {
        fai += g_colsum[b * NN + j];
        float4 s = sir4[j];
        tau += s.x + s.y + s.z;
    }
#pragma unroll
    for (int o = 16; o; o >>= 1) {
        fai += __shfl_down_sync(0xFFFFFFFFu, fai, o);
        tau += __shfl_down_sync(0xFFFFFFFFu, tau, o);
    }
    __shared__ float shF[8], shT[8];
    const int w = t >> 5, l = t & 31;
    if (l == 0) { shF[w] = fai; shT[w] = tau; }
    __syncthreads();
    if (t == 0) {
        float F = 0.0f, T = 0.0f;
#pragma unroll
        for (int k = 0; k < 8; ++k) { F += shF[k]; T += shT[k]; }
        g_m[b] = F / T;
    }
}

// ---------------------------------------------------------------------------
// Kernel 3: main streaming pass. One warp per row i.
// SIR staged in shared as SoA (sS/sI/sR) so lane-strided float4 LDS is
// conflict-free (16B lane stride -> 8-lane phase covers banks 0..31).
// Output layout: [Ht_SIR (B*N*6)] [arrive1 (B*N*4)] [arrive2 (B*N*N*2)]
// ---------------------------------------------------------------------------
__global__ void __launch_bounds__(256) main_kernel(
    const float* __restrict__ param_b, const float* __restrict__ contact,
    const float* __restrict__ mob, const float* __restrict__ SIR,
    const float* __restrict__ sps, const float* __restrict__ birth,
    const float* __restrict__ death, float* __restrict__ out)
{
    __shared__ float sS[NN], sI[NN], sR[NN];   // 24 KB

    const int b = blockIdx.y;
    const int t = threadIdx.x;

    const float4* sir4 = (const float4*)(SIR + (size_t)b * NN * 4);
    for (int j = t; j < NN; j += 256) {
        float4 s = sir4[j];
        sS[j] = s.x; sI[j] = s.y; sR[j] = s.z;
    }
    __syncthreads();

    const int wid  = t >> 5;
    const int lane = t & 31;
    const int i    = blockIdx.x * 8 + wid;

    const float rcs = 1.0f / g_colsum[b * NN + i];
    const float m_b = g_m[b];

    const float4* mobr = (const float4*)(mob + ((size_t)b * NN + i) * NN);
    const float4* spsr = (const float4*)(sps + ((size_t)b * NN + i) * NN);
    const float4* sS4  = (const float4*)sS;
    const float4* sI4  = (const float4*)sI;
    const float4* sR4  = (const float4*)sR;
    const size_t OFF2 = (size_t)BB * NN * 6 + (size_t)BB * NN * 4;
    float4* out2 = (float4*)(out + OFF2 + ((size_t)b * NN + i) * (size_t)NN * 2);

    float fS = 0.0f, fI = 0.0f, fR = 0.0f;

#pragma unroll 4
    for (int k = lane; k < NN / 4; k += 32) {
        float4 f  = mobr[k];
        float4 sp = spsr[k];
        const int j0 = k * 4;
        if (j0     == i) { f.x = 0.0f; sp.x = 0.0f; }
        if (j0 + 1 == i) { f.y = 0.0f; sp.y = 0.0f; }
        if (j0 + 2 == i) { f.z = 0.0f; sp.z = 0.0f; }
        if (j0 + 3 == i) { f.w = 0.0f; sp.w = 0.0f; }

        const float4 vS = sS4[k];
        const float4 vI = sI4[k];
        const float4 vR = sR4[k];

        fS += f.x * vS.x + f.y * vS.y + f.z * vS.z + f.w * vS.w;
        fI += f.x * vI.x + f.y * vI.y + f.z * vI.z + f.w * vI.w;
        fR += f.x * vR.x + f.y * vR.y + f.z * vR.z + f.w * vR.w;

        out2[2 * k]     = make_float4(sp.x, f.x * rcs, sp.y, f.y * rcs);
        out2[2 * k + 1] = make_float4(sp.z, f.z * rcs, sp.w, f.w * rcs);
    }

#pragma unroll
    for (int o = 16; o; o >>= 1) {
        fS += __shfl_down_sync(0xFFFFFFFFu, fS, o);
        fI += __shfl_down_sync(0xFFFFFFFFu, fI, o);
        fR += __shfl_down_sync(0xFFFFFFFFu, fR, o);
    }

    if (lane == 0) {
        const float S = sS[i], I = sI[i], R = sR[i];
        const float Isum = SIR[((size_t)b * NN + i) * 4 + 3];
        const float pop = S + I + R;
        const float pb  = param_b[b * NN + i];
        const float ct  = contact[b * NN + i];
        const float dth = death[i];
        const float brt = birth[i];

        const float fluxS = m_b * rcs * fS;
        const float fluxI = m_b * rcs * fI;
        const float fluxR = m_b * rcs * fR;

        const float I_new  = S / pop * pb * ct * I;
        const float R_t    = R + PARAM_G * I - dth * R - m_b * R + fluxR;
        const float I_t    = I + I_new - dth * I - PARAM_G * I - VIRUS_DEATH * I - m_b * I + fluxI;
        const float S_t    = S - I_new - dth * S + brt * pop - m_b * S + fluxS;
        const float Isum_t = Isum + I_new;
        const float R0     = pb * ct / (dth + PARAM_G + VIRUS_DEATH + m_b);
        const float W      = pb * ct - dth - PARAM_G - VIRUS_DEATH;

        float* ht = out + (size_t)(b * NN + i) * 6;
        ht[0] = R0;  ht[1] = I_new; ht[2] = S_t;
        ht[3] = I_t; ht[4] = R_t;   ht[5] = Isum_t;

        float* a1 = out + (size_t)BB * NN * 6 + (size_t)(b * NN + i) * 4;
        a1[0] = W; a1[1] = m_b; a1[2] = I; a1[3] = pop;
    }
}

// ---------------------------------------------------------------------------
extern "C" void kernel_launch(void* const* d_in, const int* in_sizes, int n_in,
                              void* d_out, int out_size) {
    const float* param_b = (const float*)d_in[0];
    const float* contact = (const float*)d_in[1];
    const float* mob     = (const float*)d_in[2];
    const float* SIR     = (const float*)d_in[3];
    const float* sps     = (const float*)d_in[4];
    const float* birth   = (const float*)d_in[5];
    const float* death   = (const float*)d_in[6];
    float* out = (float*)d_out;

    zero_kernel<<<(BB * NN + 255) / 256, 256>>>();
    colsum_kernel<<<dim3(NN / 1024, 16, BB), 256>>>(mob);
    m_kernel<<<BB, 256>>>(SIR);
    main_kernel<<<dim3(NN / 8, BB), 256>>>(param_b, contact, mob, SIR, sps,
                                           birth, death, out);
}

// round 3
// speedup vs baseline: 1.0316x; 1.0316x over previous
#include <cuda_runtime.h>
#include <cuda_bf16.h>

#define BB 4
#define NN 2048
#define PARAM_G 0.125f
#define VIRUS_DEATH 8e-05f

// Scratch (allocation-free rule: __device__ globals)
__device__ float g_colsum[BB * NN];
__device__ float g_m[BB];
__device__ float g_fS[BB * NN];   // rcs * sum_j F[i][j]*S[j]
__device__ float g_fI[BB * NN];
__device__ float g_fR[BB * NN];

// ---------------------------------------------------------------------------
// Kernel 0: zero the column-sum scratch (must be reset every graph replay)
// ---------------------------------------------------------------------------
__global__ void zero_kernel() {
    int t = blockIdx.x * blockDim.x + threadIdx.x;
    if (t < BB * NN) g_colsum[t] = 0.0f;
}

// ---------------------------------------------------------------------------
// Kernel 1: col_sum[b][j] = sum_{i != j} mob[b][i][j]
// Thread = 4 columns (float4, coalesced), each block covers a 32-row chunk.
// 512 CTAs -> full-chip, enough in-flight loads to cover DRAM latency.
// ---------------------------------------------------------------------------
__global__ void __launch_bounds__(256) colsum_kernel(const float* __restrict__ mob) {
    const int t  = threadIdx.x;
    const int c4 = blockIdx.x * 256 + t;          // float4 column group
    const int j0 = c4 * 4;                        // first of 4 columns
    const int b  = blockIdx.z;
    const int i0 = blockIdx.y * (NN / 64);
    const float4* base = (const float4*)(mob + (size_t)b * NN * NN) + c4;
    float4 s = make_float4(0.f, 0.f, 0.f, 0.f);
#pragma unroll 8
    for (int i = i0; i < i0 + NN / 64; ++i) {
        float4 v = base[(size_t)i * (NN / 4)];
        if (i == j0)     v.x = 0.0f;
        if (i == j0 + 1) v.y = 0.0f;
        if (i == j0 + 2) v.z = 0.0f;
        if (i == j0 + 3) v.w = 0.0f;
        s.x += v.x; s.y += v.y; s.z += v.z; s.w += v.w;
    }
    float* dst = &g_colsum[b * NN + j0];
    atomicAdd(dst + 0, s.x);
    atomicAdd(dst + 1, s.y);
    atomicAdd(dst + 2, s.z);
    atomicAdd(dst + 3, s.w);
}

// ---------------------------------------------------------------------------
// Kernel 2: per batch, fai = sum(col_sum), tau = sum(S+I+R), m = fai/tau
// ---------------------------------------------------------------------------
__global__ void __launch_bounds__(256) m_kernel(const float* __restrict__ SIR) {
    const int b = blockIdx.x;
    const int t = threadIdx.x;
    const float4* sir4 = (const float4*)(SIR + (size_t)b * NN * 4);
    float fai = 0.0f, tau = 0.0f;
    for (int j = t; j < NN; j += 256) {
        fai += g_colsum[b * NN + j];
        float4 s = sir4[j];
        tau += s.x + s.y + s.z;
    }
#pragma unroll
    for (int o = 16; o; o >>= 1) {
        fai += __shfl_down_sync(0xFFFFFFFFu, fai, o);
        tau += __shfl_down_sync(0xFFFFFFFFu, tau, o);
    }
    __shared__ float shF[8], shT[8];
    const int w = t >> 5, l = t & 31;
    if (l == 0) { shF[w] = fai; shT[w] = tau; }
    __syncthreads();
    if (t == 0) {
        float F = 0.0f, T = 0.0f;
#pragma unroll
        for (int k = 0; k < 8; ++k) { F += shF[k]; T += shT[k]; }
        g_m[b] = F / T;
    }
}

// ---------------------------------------------------------------------------
// Kernel 3: main streaming pass. One warp per row i. Matvec + arrive2 only;
// per-node epilogue math moved to a separate kernel to cut register pressure.
// sps read with .cs (single-use), arrive2 written with .cs (evict-first) so
// the 134MB write stream does not evict mob from L2 (mob re-read after colsum).
// Output layout: [Ht_SIR (B*N*6)] [arrive1 (B*N*4)] [arrive2 (B*N*N*2)]
// ---------------------------------------------------------------------------
__global__ void __launch_bounds__(256, 5) main_kernel(
    const float* __restrict__ mob, const float* __restrict__ SIR,
    const float* __restrict__ sps, float* __restrict__ out)
{
    __shared__ float sS[NN], sI[NN], sR[NN];   // 24 KB

    const int b = blockIdx.y;
    const int t = threadIdx.x;

    const float4* sir4 = (const float4*)(SIR + (size_t)b * NN * 4);
    for (int j = t; j < NN; j += 256) {
        float4 s = sir4[j];
        sS[j] = s.x; sI[j] = s.y; sR[j] = s.z;
    }
    __syncthreads();

    const int wid  = t >> 5;
    const int lane = t & 31;
    const int i    = blockIdx.x * 8 + wid;

    const float rcs = 1.0f / g_colsum[b * NN + i];

    const float4* mobr = (const float4*)(mob + ((size_t)b * NN + i) * NN);
    const float4* spsr = (const float4*)(sps + ((size_t)b * NN + i) * NN);
    const float4* sS4  = (const float4*)sS;
    const float4* sI4  = (const float4*)sI;
    const float4* sR4  = (const float4*)sR;
    const size_t OFF2 = (size_t)BB * NN * 6 + (size_t)BB * NN * 4;
    float4* out2 = (float4*)(out + OFF2 + ((size_t)b * NN + i) * (size_t)NN * 2);

    float fS = 0.0f, fI = 0.0f, fR = 0.0f;

#pragma unroll 4
    for (int k = lane; k < NN / 4; k += 32) {
        float4 f  = __ldcs(&mobr[k]);   // last use of mob -> evict-first
        float4 sp = __ldcs(&spsr[k]);   // single use -> evict-first
        const int j0 = k * 4;
        if (j0     == i) { f.x = 0.0f; sp.x = 0.0f; }
        if (j0 + 1 == i) { f.y = 0.0f; sp.y = 0.0f; }
        if (j0 + 2 == i) { f.z = 0.0f; sp.z = 0.0f; }
        if (j0 + 3 == i) { f.w = 0.0f; sp.w = 0.0f; }

        const float4 vS = sS4[k];
        const float4 vI = sI4[k];
        const float4 vR = sR4[k];

        fS += f.x * vS.x + f.y * vS.y + f.z * vS.z + f.w * vS.w;
        fI += f.x * vI.x + f.y * vI.y + f.z * vI.z + f.w * vI.w;
        fR += f.x * vR.x + f.y * vR.y + f.z * vR.z + f.w * vR.w;

        __stcs(&out2[2 * k],     make_float4(sp.x, f.x * rcs, sp.y, f.y * rcs));
        __stcs(&out2[2 * k + 1], make_float4(sp.z, f.z * rcs, sp.w, f.w * rcs));
    }

#pragma unroll
    for (int o = 16; o; o >>= 1) {
        fS += __shfl_down_sync(0xFFFFFFFFu, fS, o);
        fI += __shfl_down_sync(0xFFFFFFFFu, fI, o);
        fR += __shfl_down_sync(0xFFFFFFFFu, fR, o);
    }

    if (lane == 0) {
        const int gi = b * NN + i;
        g_fS[gi] = rcs * fS;
        g_fI[gi] = rcs * fI;
        g_fR[gi] = rcs * fR;
    }
}

// ---------------------------------------------------------------------------
// Kernel 4: per-node epilogue. Thread per (b,i).
// ---------------------------------------------------------------------------
__global__ void __launch_bounds__(256) epi_kernel(
    const float* __restrict__ param_b, const float* __restrict__ contact,
    const float* __restrict__ SIR, const float* __restrict__ birth,
    const float* __restrict__ death, float* __restrict__ out)
{
    const int g = blockIdx.x * 256 + threadIdx.x;
    if (g >= BB * NN) return;
    const int b = g / NN;
    const int i = g - b * NN;

    const float4 sir = ((const float4*)SIR)[g];
    const float S = sir.x, I = sir.y, R = sir.z, Isum = sir.w;
    const float pop = S + I + R;
    const float pb  = param_b[g];
    const float ct  = contact[g];
    const float dth = death[i];
    const float brt = birth[i];
    const float m_b = g_m[b];

    const float fluxS = m_b * g_fS[g];
    const float fluxI = m_b * g_fI[g];
    const float fluxR = m_b * g_fR[g];

    const float I_new  = S / pop * pb * ct * I;
    const float R_t    = R + PARAM_G * I - dth * R - m_b * R + fluxR;
    const float I_t    = I + I_new - dth * I - PARAM_G * I - VIRUS_DEATH * I - m_b * I + fluxI;
    const float S_t    = S - I_new - dth * S + brt * pop - m_b * S + fluxS;
    const float Isum_t = Isum + I_new;
    const float R0     = pb * ct / (dth + PARAM_G + VIRUS_DEATH + m_b);
    const float W      = pb * ct - dth - PARAM_G - VIRUS_DEATH;

    float* ht = out + (size_t)g * 6;
    ht[0] = R0;  ht[1] = I_new; ht[2] = S_t;
    ht[3] = I_t; ht[4] = R_t;   ht[5] = Isum_t;

    ((float4*)(out + (size_t)BB * NN * 6))[g] = make_float4(W, m_b, I, pop);
}

// ---------------------------------------------------------------------------
extern "C" void kernel_launch(void* const* d_in, const int* in_sizes, int n_in,
                              void* d_out, int out_size) {
    const float* param_b = (const float*)d_in[0];
    const float* contact = (const float*)d_in[1];
    const float* mob     = (const float*)d_in[2];
    const float* SIR     = (const float*)d_in[3];
    const float* sps     = (const float*)d_in[4];
    const float* birth   = (const float*)d_in[5];
    const float* death   = (const float*)d_in[6];
    float* out = (float*)d_out;

    zero_kernel<<<(BB * NN + 255) / 256, 256>>>();
    colsum_kernel<<<dim3(NN / 1024, 64, BB), 256>>>(mob);
    m_kernel<<<BB, 256>>>(SIR);
    main_kernel<<<dim3(NN / 8, BB), 256>>>(mob, SIR, sps, out);
    epi_kernel<<<(BB * NN + 255) / 256, 256>>>(param_b, contact, SIR,
                                               birth, death, out);
}

// round 4
// speedup vs baseline: 1.0810x; 1.0478x over previous
#include <cuda_runtime.h>
#include <cuda_bf16.h>

#define BB 4
#define NN 2048
#define PARAM_G 0.125f
#define VIRUS_DEATH 8e-05f

// Scratch (allocation-free rule: __device__ globals)
__device__ float g_colsum[BB * NN];
__device__ float g_m[BB];
__device__ float g_fS[BB * NN];   // rcs * sum_j F[i][j]*S[j]
__device__ float g_fI[BB * NN];
__device__ float g_fR[BB * NN];

// ---------------------------------------------------------------------------
// Kernel 0: zero the column-sum scratch (must be reset every graph replay)
// ---------------------------------------------------------------------------
__global__ void zero_kernel() {
    int t = blockIdx.x * blockDim.x + threadIdx.x;
    if (t < BB * NN) g_colsum[t] = 0.0f;
}

// ---------------------------------------------------------------------------
// Kernel 1: col_sum[b][j] = sum_{i != j} mob[b][i][j]
// Thread = 4 columns (float4, coalesced), each block covers a 32-row chunk.
// 512 CTAs -> full chip, deep in-flight load queue.
// ---------------------------------------------------------------------------
__global__ void __launch_bounds__(256) colsum_kernel(const float* __restrict__ mob) {
    const int t  = threadIdx.x;
    const int c4 = blockIdx.x * 256 + t;          // float4 column group
    const int j0 = c4 * 4;                        // first of 4 columns
    const int b  = blockIdx.z;
    const int i0 = blockIdx.y * (NN / 64);
    const float4* base = (const float4*)(mob + (size_t)b * NN * NN) + c4;
    float4 s = make_float4(0.f, 0.f, 0.f, 0.f);
#pragma unroll 8
    for (int i = i0; i < i0 + NN / 64; ++i) {
        float4 v = base[(size_t)i * (NN / 4)];
        if (i == j0)     v.x = 0.0f;
        if (i == j0 + 1) v.y = 0.0f;
        if (i == j0 + 2) v.z = 0.0f;
        if (i == j0 + 3) v.w = 0.0f;
        s.x += v.x; s.y += v.y; s.z += v.z; s.w += v.w;
    }
    float* dst = &g_colsum[b * NN + j0];
    atomicAdd(dst + 0, s.x);
    atomicAdd(dst + 1, s.y);
    atomicAdd(dst + 2, s.z);
    atomicAdd(dst + 3, s.w);
}

// ---------------------------------------------------------------------------
// Kernel 2: per batch, fai = sum(col_sum), tau = sum(S+I+R), m = fai/tau
// ---------------------------------------------------------------------------
__global__ void __launch_bounds__(256) m_kernel(const float* __restrict__ SIR) {
    const int b = blockIdx.x;
    const int t = threadIdx.x;
    const float4* sir4 = (const float4*)(SIR + (size_t)b * NN * 4);
    float fai = 0.0f, tau = 0.0f;
    for (int j = t; j < NN; j += 256) {
        fai += g_colsum[b * NN + j];
        float4 s = sir4[j];
        tau += s.x + s.y + s.z;
    }
#pragma unroll
    for (int o = 16; o; o >>= 1) {
        fai += __shfl_down_sync(0xFFFFFFFFu, fai, o);
        tau += __shfl_down_sync(0xFFFFFFFFu, tau, o);
    }
    __shared__ float shF[8], shT[8];
    const int w = t >> 5, l = t & 31;
    if (l == 0) { shF[w] = fai; shT[w] = tau; }
    __syncthreads();
    if (t == 0) {
        float F = 0.0f, T = 0.0f;
#pragma unroll
        for (int k = 0; k < 8; ++k) { F += shF[k]; T += shT[k]; }
        g_m[b] = F / T;
    }
}

// ---------------------------------------------------------------------------
// Kernel 3: main streaming pass. One warp per row i.
// Two-way chunk batching per lane (k, k+32) + unroll 2 -> ~8 LDG.128 in
// flight per warp. No cache hints (R3 showed they regress the L2-warm mob).
// Output layout: [Ht_SIR (B*N*6)] [arrive1 (B*N*4)] [arrive2 (B*N*N*2)]
// ---------------------------------------------------------------------------
__global__ void __launch_bounds__(256, 4) main_kernel(
    const float* __restrict__ mob, const float* __restrict__ SIR,
    const float* __restrict__ sps, float* __restrict__ out)
{
    __shared__ float sS[NN], sI[NN], sR[NN];   // 24 KB

    const int b = blockIdx.y;
    const int t = threadIdx.x;

    const float4* sir4 = (const float4*)(SIR + (size_t)b * NN * 4);
    for (int j = t; j < NN; j += 256) {
        float4 s = sir4[j];
        sS[j] = s.x; sI[j] = s.y; sR[j] = s.z;
    }
    __syncthreads();

    const int wid  = t >> 5;
    const int lane = t & 31;
    const int i    = blockIdx.x * 8 + wid;

    const float rcs = 1.0f / g_colsum[b * NN + i];

    const float4* mobr = (const float4*)(mob + ((size_t)b * NN + i) * NN);
    const float4* spsr = (const float4*)(sps + ((size_t)b * NN + i) * NN);
    const float4* sS4  = (const float4*)sS;
    const float4* sI4  = (const float4*)sI;
    const float4* sR4  = (const float4*)sR;
    const size_t OFF2 = (size_t)BB * NN * 6 + (size_t)BB * NN * 4;
    float4* out2 = (float4*)(out + OFF2 + ((size_t)b * NN + i) * (size_t)NN * 2);

    float fS = 0.0f, fI = 0.0f, fR = 0.0f;

#pragma unroll 2
    for (int u = 0; u < 8; ++u) {
        const int k1 = lane + 64 * u;
        const int k2 = k1 + 32;

        // Front-batched loads (4 per macro-iter, 8 with unroll 2)
        float4 f1 = mobr[k1];
        float4 f2 = mobr[k2];
        float4 p1 = spsr[k1];
        float4 p2 = spsr[k2];

        const int a0 = k1 * 4, b0 = k2 * 4;
        if (a0     == i) { f1.x = 0.0f; p1.x = 0.0f; }
        if (a0 + 1 == i) { f1.y = 0.0f; p1.y = 0.0f; }
        if (a0 + 2 == i) { f1.z = 0.0f; p1.z = 0.0f; }
        if (a0 + 3 == i) { f1.w = 0.0f; p1.w = 0.0f; }
        if (b0     == i) { f2.x = 0.0f; p2.x = 0.0f; }
        if (b0 + 1 == i) { f2.y = 0.0f; p2.y = 0.0f; }
        if (b0 + 2 == i) { f2.z = 0.0f; p2.z = 0.0f; }
        if (b0 + 3 == i) { f2.w = 0.0f; p2.w = 0.0f; }

        const float4 vS1 = sS4[k1], vS2 = sS4[k2];
        const float4 vI1 = sI4[k1], vI2 = sI4[k2];
        const float4 vR1 = sR4[k1], vR2 = sR4[k2];

        fS += f1.x * vS1.x + f1.y * vS1.y + f1.z * vS1.z + f1.w * vS1.w
            + f2.x * vS2.x + f2.y * vS2.y + f2.z * vS2.z + f2.w * vS2.w;
        fI += f1.x * vI1.x + f1.y * vI1.y + f1.z * vI1.z + f1.w * vI1.w
            + f2.x * vI2.x + f2.y * vI2.y + f2.z * vI2.z + f2.w * vI2.w;
        fR += f1.x * vR1.x + f1.y * vR1.y + f1.z * vR1.z + f1.w * vR1.w
            + f2.x * vR2.x + f2.y * vR2.y + f2.z * vR2.z + f2.w * vR2.w;

        out2[2 * k1]     = make_float4(p1.x, f1.x * rcs, p1.y, f1.y * rcs);
        out2[2 * k1 + 1] = make_float4(p1.z, f1.z * rcs, p1.w, f1.w * rcs);
        out2[2 * k2]     = make_float4(p2.x, f2.x * rcs, p2.y, f2.y * rcs);
        out2[2 * k2 + 1] = make_float4(p2.z, f2.z * rcs, p2.w, f2.w * rcs);
    }

#pragma unroll
    for (int o = 16; o; o >>= 1) {
        fS += __shfl_down_sync(0xFFFFFFFFu, fS, o);
        fI += __shfl_down_sync(0xFFFFFFFFu, fI, o);
        fR += __shfl_down_sync(0xFFFFFFFFu, fR, o);
    }

    if (lane == 0) {
        const int gi = b * NN + i;
        g_fS[gi] = rcs * fS;
        g_fI[gi] = rcs * fI;
        g_fR[gi] = rcs * fR;
    }
}

// ---------------------------------------------------------------------------
// Kernel 4: per-node epilogue. Thread per (b,i).
// ---------------------------------------------------------------------------
__global__ void __launch_bounds__(256) epi_kernel(
    const float* __restrict__ param_b, const float* __restrict__ contact,
    const float* __restrict__ SIR, const float* __restrict__ birth,
    const float* __restrict__ death, float* __restrict__ out)
{
    const int g = blockIdx.x * 256 + threadIdx.x;
    if (g >= BB * NN) return;
    const int b = g / NN;
    const int i = g - b * NN;

    const float4 sir = ((const float4*)SIR)[g];
    const float S = sir.x, I = sir.y, R = sir.z, Isum = sir.w;
    const float pop = S + I + R;
    const float pb  = param_b[g];
    const float ct  = contact[g];
    const float dth = death[i];
    const float brt = birth[i];
    const float m_b = g_m[b];

    const float fluxS = m_b * g_fS[g];
    const float fluxI = m_b * g_fI[g];
    const float fluxR = m_b * g_fR[g];

    const float I_new  = S / pop * pb * ct * I;
    const float R_t    = R + PARAM_G * I - dth * R - m_b * R + fluxR;
    const float I_t    = I + I_new - dth * I - PARAM_G * I - VIRUS_DEATH * I - m_b * I + fluxI;
    const float S_t    = S - I_new - dth * S + brt * pop - m_b * S + fluxS;
    const float Isum_t = Isum + I_new;
    const float R0     = pb * ct / (dth + PARAM_G + VIRUS_DEATH + m_b);
    const float W      = pb * ct - dth - PARAM_G - VIRUS_DEATH;

    float* ht = out + (size_t)g * 6;
    ht[0] = R0;  ht[1] = I_new; ht[2] = S_t;
    ht[3] = I_t; ht[4] = R_t;   ht[5] = Isum_t;

    ((float4*)(out + (size_t)BB * NN * 6))[g] = make_float4(W, m_b, I, pop);
}

// ---------------------------------------------------------------------------
extern "C" void kernel_launch(void* const* d_in, const int* in_sizes, int n_in,
                              void* d_out, int out_size) {
    const float* param_b = (const float*)d_in[0];
    const float* contact = (const float*)d_in[1];
    const float* mob     = (const float*)d_in[2];
    const float* SIR     = (const float*)d_in[3];
    const float* sps     = (const float*)d_in[4];
    const float* birth   = (const float*)d_in[5];
    const float* death   = (const float*)d_in[6];
    float* out = (float*)d_out;

    zero_kernel<<<(BB * NN + 255) / 256, 256>>>();
    colsum_kernel<<<dim3(NN / 1024, 64, BB), 256>>>(mob);
    m_kernel<<<BB, 256>>>(SIR);
    main_kernel<<<dim3(NN / 8, BB), 256>>>(mob, SIR, sps, out);
    epi_kernel<<<(BB * NN + 255) / 256, 256>>>(param_b, contact, SIR,
                                               birth, death, out);
}

// round 5
// speedup vs baseline: 1.1190x; 1.0352x over previous
#include <cuda_runtime.h>
#include <cuda_bf16.h>

#define BB 4
#define NN 2048
#define PARAM_G 0.125f
#define VIRUS_DEATH 8e-05f
#define NCHUNK 64               // row-chunks for colsum partials

// Scratch (allocation-free rule: __device__ globals). All fully overwritten
// each replay -> no zeroing, no atomics, deterministic.
__device__ float g_part[NCHUNK * BB * NN];   // colsum partials [chunk][b][j]
__device__ float g_colsum[BB * NN];
__device__ float g_faip[32 * BB];            // per-reduce-CTA fai partials
__device__ float g_m[BB];

// ---------------------------------------------------------------------------
// Kernel 1: colsum partials. g_part[c][b][j] = sum over 32 rows of chunk c
// of mob[b][i][j] (diagonal zeroed). Thread = 4 columns (float4), 512 CTAs.
// ---------------------------------------------------------------------------
__global__ void __launch_bounds__(256) colsum_part_kernel(const float* __restrict__ mob) {
    const int t  = threadIdx.x;
    const int c4 = blockIdx.x * 256 + t;          // float4 column group
    const int j0 = c4 * 4;
    const int b  = blockIdx.z;
    const int ch = blockIdx.y;
    const int i0 = ch * (NN / NCHUNK);
    const float4* base = (const float4*)(mob + (size_t)b * NN * NN) + c4;
    float4 s = make_float4(0.f, 0.f, 0.f, 0.f);
#pragma unroll 8
    for (int i = i0; i < i0 + NN / NCHUNK; ++i) {
        float4 v = base[(size_t)i * (NN / 4)];
        if (i == j0)     v.x = 0.0f;
        if (i == j0 + 1) v.y = 0.0f;
        if (i == j0 + 2) v.z = 0.0f;
        if (i == j0 + 3) v.w = 0.0f;
        s.x += v.x; s.y += v.y; s.z += v.z; s.w += v.w;
    }
    ((float4*)g_part)[((ch * BB + b) * NN) / 4 + c4] = s;
}

// ---------------------------------------------------------------------------
// Kernel 2: fold partials -> g_colsum[b][j]; also per-CTA fai partials.
// Grid 32 CTAs: blockIdx.x = b*8 + colblock (256 cols per CTA, thread=1 col).
// ---------------------------------------------------------------------------
__global__ void __launch_bounds__(256) colsum_reduce_kernel() {
    const int b  = blockIdx.x >> 3;
    const int j  = (blockIdx.x & 7) * 256 + threadIdx.x;
    float s = 0.0f;
#pragma unroll
    for (int c = 0; c < NCHUNK; ++c)
        s += g_part[(c * BB + b) * NN + j];
    g_colsum[b * NN + j] = s;

    // block-reduce s -> fai partial
#pragma unroll
    for (int o = 16; o; o >>= 1) s += __shfl_down_sync(0xFFFFFFFFu, s, o);
    __shared__ float sh[8];
    const int w = threadIdx.x >> 5, l = threadIdx.x & 31;
    if (l == 0) sh[w] = s;
    __syncthreads();
    if (threadIdx.x == 0) {
        float F = 0.0f;
#pragma unroll
        for (int k = 0; k < 8; ++k) F += sh[k];
        g_faip[blockIdx.x] = F;
    }
}

// ---------------------------------------------------------------------------
// Kernel 3: per batch, fai = sum of 8 partials, tau = sum(S+I+R), m = fai/tau
// ---------------------------------------------------------------------------
__global__ void __launch_bounds__(256) m_kernel(const float* __restrict__ SIR) {
    const int b = blockIdx.x;
    const int t = threadIdx.x;
    const float4* sir4 = (const float4*)(SIR + (size_t)b * NN * 4);
    float tau = 0.0f;
    for (int j = t; j < NN; j += 256) {
        float4 s = sir4[j];
        tau += s.x + s.y + s.z;
    }
#pragma unroll
    for (int o = 16; o; o >>= 1) tau += __shfl_down_sync(0xFFFFFFFFu, tau, o);
    __shared__ float shT[8];
    const int w = t >> 5, l = t & 31;
    if (l == 0) shT[w] = tau;
    __syncthreads();
    if (t == 0) {
        float T = 0.0f;
#pragma unroll
        for (int k = 0; k < 8; ++k) T += shT[k];
        float F = 0.0f;
#pragma unroll
        for (int k = 0; k < 8; ++k) F += g_faip[b * 8 + k];
        g_m[b] = F / T;
    }
}

// ---------------------------------------------------------------------------
// Kernel 4: main streaming pass (R2 body — fastest measured). One warp per
// row i; SoA smem SIR (conflict-free LDS.128); fused lane-0 epilogue.
// Output layout: [Ht_SIR (B*N*6)] [arrive1 (B*N*4)] [arrive2 (B*N*N*2)]
// ---------------------------------------------------------------------------
__global__ void __launch_bounds__(256) main_kernel(
    const float* __restrict__ param_b, const float* __restrict__ contact,
    const float* __restrict__ mob, const float* __restrict__ SIR,
    const float* __restrict__ sps, const float* __restrict__ birth,
    const float* __restrict__ death, float* __restrict__ out)
{
    __shared__ float sS[NN], sI[NN], sR[NN];   // 24 KB

    const int b = blockIdx.y;
    const int t = threadIdx.x;

    const float4* sir4 = (const float4*)(SIR + (size_t)b * NN * 4);
    for (int j = t; j < NN; j += 256) {
        float4 s = sir4[j];
        sS[j] = s.x; sI[j] = s.y; sR[j] = s.z;
    }
    __syncthreads();

    const int wid  = t >> 5;
    const int lane = t & 31;
    const int i    = blockIdx.x * 8 + wid;

    const float rcs = 1.0f / g_colsum[b * NN + i];
    const float m_b = g_m[b];

    const float4* mobr = (const float4*)(mob + ((size_t)b * NN + i) * NN);
    const float4* spsr = (const float4*)(sps + ((size_t)b * NN + i) * NN);
    const float4* sS4  = (const float4*)sS;
    const float4* sI4  = (const float4*)sI;
    const float4* sR4  = (const float4*)sR;
    const size_t OFF2 = (size_t)BB * NN * 6 + (size_t)BB * NN * 4;
    float4* out2 = (float4*)(out + OFF2 + ((size_t)b * NN + i) * (size_t)NN * 2);

    float fS = 0.0f, fI = 0.0f, fR = 0.0f;

#pragma unroll 4
    for (int k = lane; k < NN / 4; k += 32) {
        float4 f  = mobr[k];
        float4 sp = spsr[k];
        const int j0 = k * 4;
        if (j0     == i) { f.x = 0.0f; sp.x = 0.0f; }
        if (j0 + 1 == i) { f.y = 0.0f; sp.y = 0.0f; }
        if (j0 + 2 == i) { f.z = 0.0f; sp.z = 0.0f; }
        if (j0 + 3 == i) { f.w = 0.0f; sp.w = 0.0f; }

        const float4 vS = sS4[k];
        const float4 vI = sI4[k];
        const float4 vR = sR4[k];

        fS += f.x * vS.x + f.y * vS.y + f.z * vS.z + f.w * vS.w;
        fI += f.x * vI.x + f.y * vI.y + f.z * vI.z + f.w * vI.w;
        fR += f.x * vR.x + f.y * vR.y + f.z * vR.z + f.w * vR.w;

        out2[2 * k]     = make_float4(sp.x, f.x * rcs, sp.y, f.y * rcs);
        out2[2 * k + 1] = make_float4(sp.z, f.z * rcs, sp.w, f.w * rcs);
    }

#pragma unroll
    for (int o = 16; o; o >>= 1) {
        fS += __shfl_down_sync(0xFFFFFFFFu, fS, o);
        fI += __shfl_down_sync(0xFFFFFFFFu, fI, o);
        fR += __shfl_down_sync(0xFFFFFFFFu, fR, o);
    }

    if (lane == 0) {
        const float S = sS[i], I = sI[i], R = sR[i];
        const float Isum = SIR[((size_t)b * NN + i) * 4 + 3];
        const float pop = S + I + R;
        const float pb  = param_b[b * NN + i];
        const float ct  = contact[b * NN + i];
        const float dth = death[i];
        const float brt = birth[i];

        const float fluxS = m_b * rcs * fS;
        const float fluxI = m_b * rcs * fI;
        const float fluxR = m_b * rcs * fR;

        const float I_new  = S / pop * pb * ct * I;
        const float R_t    = R + PARAM_G * I - dth * R - m_b * R + fluxR;
        const float I_t    = I + I_new - dth * I - PARAM_G * I - VIRUS_DEATH * I - m_b * I + fluxI;
        const float S_t    = S - I_new - dth * S + brt * pop - m_b * S + fluxS;
        const float Isum_t = Isum + I_new;
        const float R0     = pb * ct / (dth + PARAM_G + VIRUS_DEATH + m_b);
        const float W      = pb * ct - dth - PARAM_G - VIRUS_DEATH;

        float* ht = out + (size_t)(b * NN + i) * 6;
        ht[0] = R0;  ht[1] = I_new; ht[2] = S_t;
        ht[3] = I_t; ht[4] = R_t;   ht[5] = Isum_t;

        float* a1 = out + (size_t)BB * NN * 6 + (size_t)(b * NN + i) * 4;
        a1[0] = W; a1[1] = m_b; a1[2] = I; a1[3] = pop;
    }
}

// ---------------------------------------------------------------------------
extern "C" void kernel_launch(void* const* d_in, const int* in_sizes, int n_in,
                              void* d_out, int out_size) {
    const float* param_b = (const float*)d_in[0];
    const float* contact = (const float*)d_in[1];
    const float* mob     = (const float*)d_in[2];
    const float* SIR     = (const float*)d_in[3];
    const float* sps     = (const float*)d_in[4];
    const float* birth   = (const float*)d_in[5];
    const float* death   = (const float*)d_in[6];
    float* out = (float*)d_out;

    colsum_part_kernel<<<dim3(NN / 1024, NCHUNK, BB), 256>>>(mob);
    colsum_reduce_kernel<<<32, 256>>>();
    m_kernel<<<BB, 256>>>(SIR);
    main_kernel<<<dim3(NN / 8, BB), 256>>>(param_b, contact, mob, SIR, sps,
                                           birth, death, out);
}